// round 4
// baseline (speedup 1.0000x reference)
#include <cuda_runtime.h>
#include <cuda_bf16.h>
#include <cstdint>

// ---------------- problem constants ----------------
#define C_IN   256
#define C_OUT  256
#define HW     4096
#define KTAPS  9
#define KTOT   2304          // tap-major: kord = tap*256 + c
#define MTOT   16384

// ---------------- GEMM tiling ----------------
#define BM 64
#define BN 256
#define BK 64
#define NCHUNK 36            // KTOT/BK

#define PITCH  144           // 64 ch * 2B + 16B pad  (conflict-free, 16B aligned)
#define ABUF   (BM * PITCH)  // 9216
#define BBUF   (BN * PITCH)  // 36864

#define AH_OFF    0
#define AL_OFF    9216
#define BH_OFF    18432
#define BL_OFF    55296
#define PARAM_OFF 92160      // 64 * 32B
#define SMEM_TOTAL 94208

#define CS_PITCH 65

// ---------------- device scratch ----------------
__device__ float    g_xT[4 * HW * C_IN];                 // NHWC, 16MB
__device__ __align__(16) uint16_t g_wBh[C_OUT * KTOT];   // bf16 hi, [o][kord]
__device__ __align__(16) uint16_t g_wBl[C_OUT * KTOT];   // bf16 lo

// ---------------- prep kernels ----------------
__global__ void prep_w(const float* __restrict__ w) {
    int i = blockIdx.x * 256 + threadIdx.x;      // over C_OUT*KTOT
    int kord = i % KTOT;
    int o    = i / KTOT;
    int tap  = kord >> 8;
    int c    = kord & 255;
    float v = w[o * KTOT + c * KTAPS + tap];
    __nv_bfloat16 h = __float2bfloat16_rn(v);
    float r = v - __bfloat162float(h);
    __nv_bfloat16 l = __float2bfloat16_rn(r);
    g_wBh[i] = *(uint16_t*)&h;
    g_wBl[i] = *(uint16_t*)&l;
}

__global__ void transpose_x(const float* __restrict__ x) {
    __shared__ float t[32][33];
    const int b   = blockIdx.z;
    const int hw0 = blockIdx.x * 32;
    const int c0  = blockIdx.y * 32;
    const int tx  = threadIdx.x, ty = threadIdx.y;
    #pragma unroll
    for (int i = 0; i < 4; ++i)
        t[ty + i * 8][tx] = x[((b * C_IN + c0 + ty + i * 8) << 12) + hw0 + tx];
    __syncthreads();
    #pragma unroll
    for (int i = 0; i < 4; ++i)
        g_xT[b * (HW * C_IN) + (hw0 + ty + i * 8) * C_IN + c0 + tx] =
            t[tx][ty + i * 8];
}

// ---------------- asm helpers ----------------
__device__ __forceinline__ uint32_t smem_u32(const void* p) {
    uint32_t a;
    asm("{ .reg .u64 t; cvta.to.shared.u64 t, %1; cvt.u32.u64 %0, t; }"
        : "=r"(a) : "l"(p));
    return a;
}
__device__ __forceinline__ void ldsm4(uint32_t* r, uint32_t a) {
    asm volatile("ldmatrix.sync.aligned.m8n8.x4.shared.b16 {%0,%1,%2,%3}, [%4];"
                 : "=r"(r[0]), "=r"(r[1]), "=r"(r[2]), "=r"(r[3]) : "r"(a));
}
__device__ __forceinline__ void hmma(float* d, const uint32_t* a,
                                     uint32_t b0, uint32_t b1) {
    asm volatile(
        "mma.sync.aligned.m16n8k16.row.col.f32.bf16.bf16.f32 "
        "{%0,%1,%2,%3}, {%4,%5,%6,%7}, {%8,%9}, {%0,%1,%2,%3};"
        : "+f"(d[0]), "+f"(d[1]), "+f"(d[2]), "+f"(d[3])
        : "r"(a[0]), "r"(a[1]), "r"(a[2]), "r"(a[3]), "r"(b0), "r"(b1));
}
__device__ __forceinline__ void cpasync16(uint32_t dst, const void* src) {
    asm volatile("cp.async.cg.shared.global [%0], [%1], 16;"
                 :: "r"(dst), "l"(src) : "memory");
}

// ---------------- main kernel ----------------
__global__ __launch_bounds__(256, 2)
void dconv_mma(const float* __restrict__ off,
               const float* __restrict__ bias,
               float* __restrict__ out)
{
    extern __shared__ char smem[];
    const uint32_t sbase = smem_u32(smem);
    const int tid = threadIdx.x;
    const int wid = tid >> 5;
    const int lid = tid & 31;

    const int b   = blockIdx.x >> 6;           // image
    const int hw0 = (blockIdx.x & 63) << 6;    // first position of tile (64)
    const char* xTb = (const char*)g_xT + ((size_t)b << 22);

    // warp tile: M32 x N64
    const int mrow = (wid & 1) * 32;
    const int ncol = (wid >> 1) * 64;
    const uint32_t aoff = (uint32_t)(lid & 15) * PITCH + (uint32_t)(lid >> 4) * 16;
    // B ldsm.x4: lanes0-7 n rows (k lo), 8-15 (k hi), 16-23 n+8 (k lo), 24-31 (k hi)
    const uint32_t boff = (uint32_t)(lid & 7) * PITCH
                        + (uint32_t)((lid >> 3) & 1) * 16
                        + (uint32_t)(lid >> 4) * (8 * PITCH);

    float acc[2][8][4];
    #pragma unroll
    for (int i = 0; i < 2; ++i)
        #pragma unroll
        for (int j = 0; j < 8; ++j)
            #pragma unroll
            for (int k = 0; k < 4; ++k) acc[i][j][k] = 0.f;

    #pragma unroll 1
    for (int chunk = 0; chunk < NCHUNK; ++chunk) {
        // ---- param table for new tap (every 4 chunks) ----
        if ((chunk & 3) == 0) {
            const int tap = chunk >> 2;
            if (tid < 64) {
                const int pos = tid;
                const int hw  = hw0 + pos;
                const int ho  = hw >> 6, wo = hw & 63;
                const float offy = off[((b * 18 + 2 * tap)     << 12) + hw];
                const float offx = off[((b * 18 + 2 * tap + 1) << 12) + hw];
                const float py = (float)(ho - 1 + tap / 3) + offy;
                const float px = (float)(wo - 1 + tap % 3) + offx;
                const float y0f = floorf(py), x0f = floorf(px);
                const int y0 = (int)y0f, x0 = (int)x0f;
                const float fy = py - y0f, fx = px - x0f;
                float w00 = (1.f - fy) * (1.f - fx), w01 = (1.f - fy) * fx;
                float w10 = fy * (1.f - fx),         w11 = fy * fx;
                const bool vy0 = (unsigned)y0 < 64u, vy1 = (unsigned)(y0 + 1) < 64u;
                const bool vx0 = (unsigned)x0 < 64u, vx1 = (unsigned)(x0 + 1) < 64u;
                if (!(vy0 && vx0)) w00 = 0.f;
                if (!(vy0 && vx1)) w01 = 0.f;
                if (!(vy1 && vx0)) w10 = 0.f;
                if (!(vy1 && vx1)) w11 = 0.f;
                const int cy0 = min(max(y0, 0), 63), cy1 = min(max(y0 + 1, 0), 63);
                const int cx0 = min(max(x0, 0), 63), cx1 = min(max(x0 + 1, 0), 63);
                const int o00 = (cy0 * 64 + cx0) << 10, o01 = (cy0 * 64 + cx1) << 10;
                const int o10 = (cy1 * 64 + cx0) << 10, o11 = (cy1 * 64 + cx1) << 10;
                char* pp = smem + PARAM_OFF + pos * 32;
                *(float4*)pp      = make_float4(w00, w01, w10, w11);
                *(int4*)(pp + 16) = make_int4(o00, o01, o10, o11);
            }
            __syncthreads();
        }

        // ---- B fill via cp.async (overlaps with A gather below) ----
        {
            const int ke = chunk * 64;
            #pragma unroll
            for (int i = 0; i < 8; ++i) {
                const int id = tid + (i << 8);
                const int n = id >> 3, s = id & 7;
                const uint32_t d0 = sbase + (uint32_t)(n * PITCH + s * 16);
                cpasync16(d0 + BH_OFF, g_wBh + n * KTOT + ke + s * 8);
                cpasync16(d0 + BL_OFF, g_wBl + n * KTOT + ke + s * 8);
            }
            asm volatile("cp.async.commit_group;" ::: "memory");
        }

        // ---- A fill: bilinear gather from NHWC, split to bf16 hi/lo ----
        {
            char* ah = smem + AH_OFF;
            char* al = smem + AL_OFF;
            const int chb = ((chunk & 3) << 8);   // byte offset of chunk's 64 ch
            const int psub = lid >> 3;
            const int q    = lid & 7;
            #pragma unroll
            for (int it = 0; it < 2; ++it) {
                const int pos = (wid << 3) + (it << 2) + psub;
                const char* pp = smem + PARAM_OFF + pos * 32;
                const float4 wv = *(const float4*)pp;
                const int4  ov = *(const int4*)(pp + 16);
                const char* src = xTb + chb + q * 16;
                #pragma unroll
                for (int hh = 0; hh < 2; ++hh) {
                    const int co = hh * 128;
                    const float4 a0 = *(const float4*)(src + ov.x + co);
                    const float4 a1 = *(const float4*)(src + ov.y + co);
                    const float4 a2 = *(const float4*)(src + ov.z + co);
                    const float4 a3 = *(const float4*)(src + ov.w + co);
                    float4 v;
                    v.x = wv.x*a0.x + wv.y*a1.x + wv.z*a2.x + wv.w*a3.x;
                    v.y = wv.x*a0.y + wv.y*a1.y + wv.z*a2.y + wv.w*a3.y;
                    v.z = wv.x*a0.z + wv.y*a1.z + wv.z*a2.z + wv.w*a3.z;
                    v.w = wv.x*a0.w + wv.y*a1.w + wv.z*a2.w + wv.w*a3.w;
                    __nv_bfloat162 h0 = __floats2bfloat162_rn(v.x, v.y);
                    __nv_bfloat162 h1 = __floats2bfloat162_rn(v.z, v.w);
                    __nv_bfloat162 l0 = __floats2bfloat162_rn(
                        v.x - __bfloat162float(h0.x), v.y - __bfloat162float(h0.y));
                    __nv_bfloat162 l1 = __floats2bfloat162_rn(
                        v.z - __bfloat162float(h1.x), v.w - __bfloat162float(h1.y));
                    const int dsto = pos * PITCH + hh * 64 + q * 8;
                    *(uint2*)(ah + dsto) = make_uint2(*(uint32_t*)&h0, *(uint32_t*)&h1);
                    *(uint2*)(al + dsto) = make_uint2(*(uint32_t*)&l0, *(uint32_t*)&l1);
                }
            }
        }
        asm volatile("cp.async.wait_group 0;" ::: "memory");
        __syncthreads();

        // ---- MMA ----
        {
            const uint32_t sAh = sbase + AH_OFF + mrow * PITCH + aoff;
            const uint32_t sAl = sbase + AL_OFF + mrow * PITCH + aoff;
            const uint32_t sBh = sbase + BH_OFF + ncol * PITCH + boff;
            const uint32_t sBl = sbase + BL_OFF + ncol * PITCH + boff;
            #pragma unroll
            for (int ks = 0; ks < 4; ++ks) {
                const uint32_t ka = ks * 32;
                uint32_t ahf[2][4], alf[2][4];
                #pragma unroll
                for (int ms = 0; ms < 2; ++ms) {
                    ldsm4(ahf[ms], sAh + ms * (16 * PITCH) + ka);
                    ldsm4(alf[ms], sAl + ms * (16 * PITCH) + ka);
                }
                #pragma unroll
                for (int np = 0; np < 4; ++np) {
                    uint32_t bh4[4], bl4[4];
                    ldsm4(bh4, sBh + np * (16 * PITCH) + ka);
                    ldsm4(bl4, sBl + np * (16 * PITCH) + ka);
                    #pragma unroll
                    for (int ms = 0; ms < 2; ++ms) {
                        hmma(acc[ms][np * 2],     ahf[ms], bh4[0], bh4[1]);
                        hmma(acc[ms][np * 2 + 1], ahf[ms], bh4[2], bh4[3]);
                        hmma(acc[ms][np * 2],     ahf[ms], bl4[0], bl4[1]);
                        hmma(acc[ms][np * 2 + 1], ahf[ms], bl4[2], bl4[3]);
                        hmma(acc[ms][np * 2],     alf[ms], bh4[0], bh4[1]);
                        hmma(acc[ms][np * 2 + 1], alf[ms], bh4[2], bh4[3]);
                    }
                }
            }
        }
        __syncthreads();
    }

    // ---- epilogue: transpose through smem, coalesced stores ----
    float* csf = (float*)smem;
    const int g  = lid >> 2;
    const int t2 = (lid & 3) * 2;
    const int outbase = (b << 20) + hw0;
    #pragma unroll 1
    for (int p = 0; p < 8; ++p) {
        if ((wid >> 1) == (p >> 1)) {
            const int nsb = (p & 1) * 4;
            #pragma unroll
            for (int ns2 = 0; ns2 < 4; ++ns2) {
                const int nl = ns2 * 8 + t2;
                #pragma unroll
                for (int ms = 0; ms < 2; ++ms) {
                    const float* a4 = acc[ms][nsb + ns2];
                    const int m = mrow + ms * 16 + g;
                    csf[nl * CS_PITCH + m]           = a4[0];
                    csf[(nl + 1) * CS_PITCH + m]     = a4[1];
                    csf[nl * CS_PITCH + m + 8]       = a4[2];
                    csf[(nl + 1) * CS_PITCH + m + 8] = a4[3];
                }
            }
        }
        __syncthreads();
        #pragma unroll
        for (int it = 0; it < 8; ++it) {
            const int e = tid + it * 256;
            const int mm = e & 63;
            const int nn = e >> 6;          // 0..31
            const int n = p * 32 + nn;
            out[outbase + (n << 12) + mm] = csf[nn * CS_PITCH + mm] + __ldg(bias + n);
        }
        __syncthreads();
    }
}

extern "C" void kernel_launch(void* const* d_in, const int* in_sizes, int n_in,
                              void* d_out, int out_size)
{
    const float* x    = (const float*)d_in[0];
    const float* off  = (const float*)d_in[1];
    const float* w    = (const float*)d_in[2];
    const float* bias = (const float*)d_in[3];
    float* out        = (float*)d_out;

    cudaFuncSetAttribute(dconv_mma, cudaFuncAttributeMaxDynamicSharedMemorySize,
                         SMEM_TOTAL);

    transpose_x<<<dim3(HW / 32, C_IN / 32, 4), dim3(32, 8)>>>(x);
    prep_w<<<(C_OUT * KTOT) / 256, 256>>>(w);
    dconv_mma<<<MTOT / BM, 256, SMEM_TOTAL>>>(off, bias, out);
}

// round 5
// speedup vs baseline: 1.4856x; 1.4856x over previous
#include <cuda_runtime.h>
#include <cuda_bf16.h>
#include <cstdint>

// ---------------- problem constants ----------------
#define C_IN   256
#define C_OUT  256
#define HW     4096
#define KTAPS  9
#define KTOT   2304          // tap-major: kord = tap*256 + c
#define MTOT   16384

// ---------------- GEMM tiling ----------------
#define BM 128
#define BN 256
#define BK 64
#define NCHUNK 36            // KTOT/BK
#define NTHREADS 512

#define PITCH  144           // 64 ch * 2B + 16B pad (conflict-free, 16B aligned)
#define ABUF   (BM * PITCH)  // 18432
#define BBUF   (BN * PITCH)  // 36864

#define AH_OFF    0          // 2 x 18432
#define AL_OFF    36864      // 2 x 18432
#define BH_OFF    73728      // 2 x 36864
#define BL_OFF    147456     // 2 x 36864
#define PARAM_OFF 221184     // 128 * 32B
#define SMEM_TOTAL 225280

#define CS_PITCH 129

// ---------------- device scratch ----------------
__device__ float    g_xT[4 * HW * C_IN];                 // NHWC, 16MB
__device__ __align__(16) uint16_t g_wBh[C_OUT * KTOT];   // bf16 hi, [o][kord]
__device__ __align__(16) uint16_t g_wBl[C_OUT * KTOT];   // bf16 lo

// ---------------- prep kernels ----------------
__global__ void prep_w(const float* __restrict__ w) {
    int i = blockIdx.x * 256 + threadIdx.x;      // over C_OUT*KTOT
    int kord = i % KTOT;
    int o    = i / KTOT;
    int tap  = kord >> 8;
    int c    = kord & 255;
    float v = w[o * KTOT + c * KTAPS + tap];
    __nv_bfloat16 h = __float2bfloat16_rn(v);
    float r = v - __bfloat162float(h);
    __nv_bfloat16 l = __float2bfloat16_rn(r);
    g_wBh[i] = *(uint16_t*)&h;
    g_wBl[i] = *(uint16_t*)&l;
}

__global__ void transpose_x(const float* __restrict__ x) {
    __shared__ float t[32][33];
    const int b   = blockIdx.z;
    const int hw0 = blockIdx.x * 32;
    const int c0  = blockIdx.y * 32;
    const int tx  = threadIdx.x, ty = threadIdx.y;
    #pragma unroll
    for (int i = 0; i < 4; ++i)
        t[ty + i * 8][tx] = x[((b * C_IN + c0 + ty + i * 8) << 12) + hw0 + tx];
    __syncthreads();
    #pragma unroll
    for (int i = 0; i < 4; ++i)
        g_xT[b * (HW * C_IN) + (hw0 + ty + i * 8) * C_IN + c0 + tx] =
            t[tx][ty + i * 8];
}

// ---------------- asm helpers ----------------
__device__ __forceinline__ uint32_t smem_u32(const void* p) {
    uint32_t a;
    asm("{ .reg .u64 t; cvta.to.shared.u64 t, %1; cvt.u32.u64 %0, t; }"
        : "=r"(a) : "l"(p));
    return a;
}
__device__ __forceinline__ void ldsm4(uint32_t* r, uint32_t a) {
    asm volatile("ldmatrix.sync.aligned.m8n8.x4.shared.b16 {%0,%1,%2,%3}, [%4];"
                 : "=r"(r[0]), "=r"(r[1]), "=r"(r[2]), "=r"(r[3]) : "r"(a));
}
__device__ __forceinline__ void hmma(float* d, const uint32_t* a,
                                     uint32_t b0, uint32_t b1) {
    asm volatile(
        "mma.sync.aligned.m16n8k16.row.col.f32.bf16.bf16.f32 "
        "{%0,%1,%2,%3}, {%4,%5,%6,%7}, {%8,%9}, {%0,%1,%2,%3};"
        : "+f"(d[0]), "+f"(d[1]), "+f"(d[2]), "+f"(d[3])
        : "r"(a[0]), "r"(a[1]), "r"(a[2]), "r"(a[3]), "r"(b0), "r"(b1));
}
__device__ __forceinline__ void cpasync16(uint32_t dst, const void* src) {
    asm volatile("cp.async.cg.shared.global [%0], [%1], 16;"
                 :: "r"(dst), "l"(src) : "memory");
}

// ---------------- main kernel ----------------
__global__ __launch_bounds__(NTHREADS, 1)
void dconv_mma(const float* __restrict__ off,
               const float* __restrict__ bias,
               float* __restrict__ out)
{
    extern __shared__ char smem[];
    const uint32_t sbase = smem_u32(smem);
    const int tid = threadIdx.x;
    const int wid = tid >> 5;
    const int lid = tid & 31;

    const int b   = blockIdx.x >> 5;           // image
    const int hw0 = (blockIdx.x & 31) << 7;    // first position of tile (128)
    const char* xTb = (const char*)g_xT + ((size_t)b << 22);

    // warp tile: M32 x N64
    const int mrow = (wid & 3) * 32;
    const int ncol = (wid >> 2) * 64;
    const uint32_t aoff = (uint32_t)(lid & 15) * PITCH + (uint32_t)(lid >> 4) * 16;
    const uint32_t boff = (uint32_t)(lid & 7) * PITCH
                        + (uint32_t)((lid >> 3) & 1) * 16
                        + (uint32_t)(lid >> 4) * (8 * PITCH);

    float acc[2][8][4];
    #pragma unroll
    for (int i = 0; i < 2; ++i)
        #pragma unroll
        for (int j = 0; j < 8; ++j)
            #pragma unroll
            for (int k = 0; k < 4; ++k) acc[i][j][k] = 0.f;

    // ---- lambdas ----
    auto param_fill = [&](int tap) {
        if (tid < 128) {
            const int pos = tid;
            const int hw  = hw0 + pos;
            const int ho  = hw >> 6, wo = hw & 63;
            const float offy = off[((b * 18 + 2 * tap)     << 12) + hw];
            const float offx = off[((b * 18 + 2 * tap + 1) << 12) + hw];
            const float py = (float)(ho - 1 + tap / 3) + offy;
            const float px = (float)(wo - 1 + tap % 3) + offx;
            const float y0f = floorf(py), x0f = floorf(px);
            const int y0 = (int)y0f, x0 = (int)x0f;
            const float fy = py - y0f, fx = px - x0f;
            float w00 = (1.f - fy) * (1.f - fx), w01 = (1.f - fy) * fx;
            float w10 = fy * (1.f - fx),         w11 = fy * fx;
            const bool vy0 = (unsigned)y0 < 64u, vy1 = (unsigned)(y0 + 1) < 64u;
            const bool vx0 = (unsigned)x0 < 64u, vx1 = (unsigned)(x0 + 1) < 64u;
            if (!(vy0 && vx0)) w00 = 0.f;
            if (!(vy0 && vx1)) w01 = 0.f;
            if (!(vy1 && vx0)) w10 = 0.f;
            if (!(vy1 && vx1)) w11 = 0.f;
            const int cy0 = min(max(y0, 0), 63), cy1 = min(max(y0 + 1, 0), 63);
            const int cx0 = min(max(x0, 0), 63), cx1 = min(max(x0 + 1, 0), 63);
            const int o00 = (cy0 * 64 + cx0) << 10, o01 = (cy0 * 64 + cx1) << 10;
            const int o10 = (cy1 * 64 + cx0) << 10, o11 = (cy1 * 64 + cx1) << 10;
            char* pp = smem + PARAM_OFF + pos * 32;
            *(float4*)pp      = make_float4(w00, w01, w10, w11);
            *(int4*)(pp + 16) = make_int4(o00, o01, o10, o11);
        }
    };

    auto fillB = [&](int chunk, int buf) {
        const int ke = chunk * 64;
        const uint32_t bh = sbase + BH_OFF + buf * BBUF;
        const uint32_t bl = sbase + BL_OFF + buf * BBUF;
        #pragma unroll
        for (int i = 0; i < 4; ++i) {
            const int id = tid + (i << 9);       // 0..2047
            const int n = id >> 3, s = id & 7;
            const uint32_t d = (uint32_t)(n * PITCH + s * 16);
            cpasync16(bh + d, g_wBh + n * KTOT + ke + s * 8);
            cpasync16(bl + d, g_wBl + n * KTOT + ke + s * 8);
        }
        asm volatile("cp.async.commit_group;" ::: "memory");
    };

    auto fillA = [&](int chunk, int buf) {
        char* ah = smem + AH_OFF + buf * ABUF;
        char* al = smem + AL_OFF + buf * ABUF;
        const int chb = (chunk & 3) << 8;        // byte offset of chunk's 64 ch
        const int pos = tid >> 2;                // 128 positions, 4 thr each
        const int qt  = tid & 3;                 // 16 channels each
        const char* pp = smem + PARAM_OFF + pos * 32;
        const float4 wv = *(const float4*)pp;
        const int4  ov = *(const int4*)(pp + 16);
        const char* src = xTb + chb + qt * 64;
        uint32_t hw_[8], lw_[8];
        #pragma unroll
        for (int j = 0; j < 4; ++j) {
            const int co = j * 16;
            const float4 a0 = *(const float4*)(src + ov.x + co);
            const float4 a1 = *(const float4*)(src + ov.y + co);
            const float4 a2 = *(const float4*)(src + ov.z + co);
            const float4 a3 = *(const float4*)(src + ov.w + co);
            float4 v;
            v.x = wv.x*a0.x + wv.y*a1.x + wv.z*a2.x + wv.w*a3.x;
            v.y = wv.x*a0.y + wv.y*a1.y + wv.z*a2.y + wv.w*a3.y;
            v.z = wv.x*a0.z + wv.y*a1.z + wv.z*a2.z + wv.w*a3.z;
            v.w = wv.x*a0.w + wv.y*a1.w + wv.z*a2.w + wv.w*a3.w;
            __nv_bfloat162 h0 = __floats2bfloat162_rn(v.x, v.y);
            __nv_bfloat162 h1 = __floats2bfloat162_rn(v.z, v.w);
            __nv_bfloat162 l0 = __floats2bfloat162_rn(
                v.x - __bfloat162float(h0.x), v.y - __bfloat162float(h0.y));
            __nv_bfloat162 l1 = __floats2bfloat162_rn(
                v.z - __bfloat162float(h1.x), v.w - __bfloat162float(h1.y));
            hw_[j*2]     = *(uint32_t*)&h0;
            hw_[j*2 + 1] = *(uint32_t*)&h1;
            lw_[j*2]     = *(uint32_t*)&l0;
            lw_[j*2 + 1] = *(uint32_t*)&l1;
        }
        const int dsto = pos * PITCH + qt * 32;
        *(uint4*)(ah + dsto)      = make_uint4(hw_[0], hw_[1], hw_[2], hw_[3]);
        *(uint4*)(ah + dsto + 16) = make_uint4(hw_[4], hw_[5], hw_[6], hw_[7]);
        *(uint4*)(al + dsto)      = make_uint4(lw_[0], lw_[1], lw_[2], lw_[3]);
        *(uint4*)(al + dsto + 16) = make_uint4(lw_[4], lw_[5], lw_[6], lw_[7]);
    };

    auto do_mma = [&](int buf) {
        const uint32_t sAh = sbase + AH_OFF + buf * ABUF + mrow * PITCH + aoff;
        const uint32_t sAl = sbase + AL_OFF + buf * ABUF + mrow * PITCH + aoff;
        const uint32_t sBh = sbase + BH_OFF + buf * BBUF + ncol * PITCH + boff;
        const uint32_t sBl = sbase + BL_OFF + buf * BBUF + ncol * PITCH + boff;
        #pragma unroll
        for (int ks = 0; ks < 4; ++ks) {
            const uint32_t ka = ks * 32;
            uint32_t ahf[2][4], alf[2][4];
            #pragma unroll
            for (int ms = 0; ms < 2; ++ms) {
                ldsm4(ahf[ms], sAh + ms * (16 * PITCH) + ka);
                ldsm4(alf[ms], sAl + ms * (16 * PITCH) + ka);
            }
            #pragma unroll
            for (int np = 0; np < 4; ++np) {
                uint32_t bh4[4], bl4[4];
                ldsm4(bh4, sBh + np * (16 * PITCH) + ka);
                ldsm4(bl4, sBl + np * (16 * PITCH) + ka);
                #pragma unroll
                for (int ms = 0; ms < 2; ++ms) {
                    hmma(acc[ms][np * 2],     ahf[ms], bh4[0], bh4[1]);
                    hmma(acc[ms][np * 2 + 1], ahf[ms], bh4[2], bh4[3]);
                    hmma(acc[ms][np * 2],     ahf[ms], bl4[0], bl4[1]);
                    hmma(acc[ms][np * 2 + 1], ahf[ms], bl4[2], bl4[3]);
                    hmma(acc[ms][np * 2],     alf[ms], bh4[0], bh4[1]);
                    hmma(acc[ms][np * 2 + 1], alf[ms], bh4[2], bh4[3]);
                }
            }
        }
    };

    // ---- pipeline: double-buffered, fill(next) overlaps mma(cur) ----
    param_fill(0);
    __syncthreads();
    fillB(0, 0);
    fillA(0, 0);
    asm volatile("cp.async.wait_group 0;" ::: "memory");
    __syncthreads();

    #pragma unroll 1
    for (int chunk = 0; chunk < NCHUNK; ++chunk) {
        const int buf = chunk & 1;
        const int nxt = chunk + 1;
        if (nxt < NCHUNK) {
            if ((nxt & 3) == 0) {
                param_fill(nxt >> 2);
                __syncthreads();
            }
            fillB(nxt, buf ^ 1);
            fillA(nxt, buf ^ 1);
        }
        do_mma(buf);
        asm volatile("cp.async.wait_group 0;" ::: "memory");
        __syncthreads();
    }

    // ---- epilogue: transpose through smem, coalesced stores ----
    float* csf = (float*)smem;
    const int g  = lid >> 2;
    const int t2 = (lid & 3) * 2;
    const int outbase = (b << 20) + hw0;
    #pragma unroll 1
    for (int p = 0; p < 8; ++p) {
        if ((wid >> 2) == (p >> 1)) {
            const int nsb = (p & 1) * 4;
            #pragma unroll
            for (int ns2 = 0; ns2 < 4; ++ns2) {
                const int nl = ns2 * 8 + t2;
                #pragma unroll
                for (int ms = 0; ms < 2; ++ms) {
                    const float* a4 = acc[ms][nsb + ns2];
                    const int m = mrow + ms * 16 + g;
                    csf[nl * CS_PITCH + m]           = a4[0];
                    csf[(nl + 1) * CS_PITCH + m]     = a4[1];
                    csf[nl * CS_PITCH + m + 8]       = a4[2];
                    csf[(nl + 1) * CS_PITCH + m + 8] = a4[3];
                }
            }
        }
        __syncthreads();
        #pragma unroll
        for (int it = 0; it < 8; ++it) {
            const int e = tid + it * NTHREADS;
            const int mm = e & 127;
            const int nn = e >> 7;          // 0..31
            const int n = p * 32 + nn;
            out[outbase + (n << 12) + mm] = csf[nn * CS_PITCH + mm] + __ldg(bias + n);
        }
        __syncthreads();
    }
}

extern "C" void kernel_launch(void* const* d_in, const int* in_sizes, int n_in,
                              void* d_out, int out_size)
{
    const float* x    = (const float*)d_in[0];
    const float* off  = (const float*)d_in[1];
    const float* w    = (const float*)d_in[2];
    const float* bias = (const float*)d_in[3];
    float* out        = (float*)d_out;

    cudaFuncSetAttribute(dconv_mma, cudaFuncAttributeMaxDynamicSharedMemorySize,
                         SMEM_TOTAL);

    transpose_x<<<dim3(HW / 32, C_IN / 32, 4), dim3(32, 8)>>>(x);
    prep_w<<<(C_OUT * KTOT) / 256, 256>>>(w);
    dconv_mma<<<MTOT / BM, NTHREADS, SMEM_TOTAL>>>(off, bias, out);
}